// round 12
// baseline (speedup 1.0000x reference)
#include <cuda_runtime.h>
#include <cuda_fp16.h>
#include <cstdint>
#include <math.h>

#define FULLMASK 0xFFFFFFFFu
#define BF    192
#define NTOK  50
#define DIM   512
#define CDIM  256
#define ROWS  (BF*NTOK)
#define NSAMP 500
#define NSPA  48
#define KSEL  12
#define NOISE_N (192u*500u*48u)

#define W_IN  0
#define W_Q   131072
#define W_K   196608
#define W_V   262144
#define W_O   327680
#define W_1A  393216
#define W_1B  458752
#define W_TOT 524288

__device__ __align__(16) __half g_a0h[ROWS*DIM];
__device__ __align__(16) __half g_a0l[ROWS*DIM];
__device__ __align__(16) __half g_wh[W_TOT];
__device__ __align__(16) __half g_wl[W_TOT];
__device__ __align__(16) __half g_h0h[ROWS*CDIM];
__device__ __align__(16) __half g_h0l[ROWS*CDIM];
__device__ __align__(16) float g_q [ROWS*CDIM];
__device__ __align__(16) float g_k [ROWS*CDIM];
__device__ __align__(16) float g_v [ROWS*CDIM];
__device__ __align__(16) __half g_aoh[ROWS*CDIM];
__device__ __align__(16) __half g_aol[ROWS*CDIM];
__device__ __align__(16) __half g_h1h[ROWS*CDIM];
__device__ __align__(16) __half g_h1l[ROWS*CDIM];
__device__ __align__(16) __half g_gmh[BF*CDIM];
__device__ __align__(16) __half g_gml[BF*CDIM];
__device__ __align__(16) float g_gb[BF*CDIM];
__device__ __align__(16) float g_h2[ROWS*CDIM];
__device__ float g_pred[ROWS];
__device__ float g_noise[NOISE_N];
__device__ float g_ind[BF*KSEL*NSPA];

__device__ __forceinline__ float gelu_f(float x){
    return 0.5f * x * (1.0f + erff(x * 0.7071067811865475f));
}
__device__ __forceinline__ void split2(float v, __half& h, __half& l){
    h = __float2half_rn(v);
    l = __float2half_rn(v - __half2float(h));
}
__device__ __forceinline__ unsigned rotl32(unsigned x, int r){
    return __funnelshift_l(x, x, r);
}
__device__ __forceinline__ void threefry(unsigned& x0, unsigned& x1){
    const unsigned ks1 = 1u, ks2 = 0x1BD11BDBu;
    x1 += ks1;
#define RND(r) { x0 += x1; x1 = rotl32(x1,(r)); x1 ^= x0; }
    RND(13) RND(15) RND(26) RND(6)
    x0 += ks1; x1 += ks2 + 1u;
    RND(17) RND(29) RND(16) RND(24)
    x0 += ks2; x1 += 2u;
    RND(13) RND(15) RND(26) RND(6)
    x1 += ks1 + 3u;
    RND(17) RND(29) RND(16) RND(24)
    x0 += ks1; x1 += ks2 + 4u;
    RND(13) RND(15) RND(26) RND(6)
    x0 += ks2; x1 += 5u;
#undef RND
}
__device__ __forceinline__ float bits_to_normal(unsigned bits){
    float f = __uint_as_float((bits >> 9) | 0x3f800000u) - 1.0f;
    const float lo = -0.99999994f;
    float u = fmaxf(lo, __fadd_rn(__fmul_rn(f, 2.0f), lo));
    return 1.4142135623730951f * erfinvf(u);
}

__global__ __launch_bounds__(256) void noise_kernel(){
    unsigned i = (blockIdx.x*256u + threadIdx.x)*4u;
    float o[4];
#pragma unroll
    for (int j=0;j<4;j++){
        unsigned x0 = 0u, x1 = i + j;
        threefry(x0, x1);
        o[j] = bits_to_normal(x0 ^ x1);
    }
    float4 v; v.x=o[0]; v.y=o[1]; v.z=o[2]; v.w=o[3];
    *(float4*)(g_noise + i) = v;
}

__global__ __launch_bounds__(256) void ln_cvt(const float* __restrict__ x,
                                              const float* __restrict__ g,
                                              const float* __restrict__ b){
    int row = (blockIdx.x*256 + threadIdx.x) >> 5;
    if (row >= ROWS) return;
    int lane = threadIdx.x & 31;
    const float* xr = x + (size_t)row*DIM;
    float vals[16], s = 0.f, s2 = 0.f;
#pragma unroll
    for (int i=0;i<16;i++){ float v = xr[lane + i*32]; vals[i]=v; s += v; s2 += v*v; }
#pragma unroll
    for (int off=16; off; off>>=1){
        s  += __shfl_xor_sync(FULLMASK, s,  off);
        s2 += __shfl_xor_sync(FULLMASK, s2, off);
    }
    float mu  = s * (1.0f/512.0f);
    float var = s2 * (1.0f/512.0f) - mu*mu;
    float rs  = rsqrtf(var + 1e-5f);
#pragma unroll
    for (int i=0;i<16;i++){
        int c = lane + i*32;
        float v = (vals[i]-mu)*rs * g[c] + b[c];
        __half h, l; split2(v, h, l);
        g_a0h[(size_t)row*DIM + c] = h;
        g_a0l[(size_t)row*DIM + c] = l;
    }
}

__global__ __launch_bounds__(256) void wcvt(const float* __restrict__ w_in,
                                            const float* __restrict__ wq,
                                            const float* __restrict__ wk,
                                            const float* __restrict__ wv,
                                            const float* __restrict__ wo,
                                            const float* __restrict__ w1){
    int idx = blockIdx.x*256 + threadIdx.x;
    if (idx >= W_TOT) return;
    float v;
    if (idx < W_Q){       int li=idx;       int n=li>>9, k=li&511; v = w_in[k*256+n]; }
    else if (idx < W_K){  int li=idx-W_Q;   int n=li>>8, k=li&255; v = wq[k*256+n]; }
    else if (idx < W_V){  int li=idx-W_K;   int n=li>>8, k=li&255; v = wk[k*256+n]; }
    else if (idx < W_O){  int li=idx-W_V;   int n=li>>8, k=li&255; v = wv[k*256+n]; }
    else if (idx < W_1A){ int li=idx-W_O;   int n=li>>8, k=li&255; v = wo[k*256+n]; }
    else if (idx < W_1B){ int li=idx-W_1A;  int n=li>>8, k=li&255; v = w1[k*256+n]; }
    else {                int li=idx-W_1B;  int n=li>>8, k=li&255; v = w1[(k+256)*256+n]; }
    __half h, l; split2(v, h, l);
    g_wh[idx] = h; g_wl[idx] = l;
}

// ===================== mma.sync fp16-split GEMM: 64x128 tile, 3-stage =======
#define STRD 40
#define A_ELEMS (64*STRD)
#define B_ELEMS (128*STRD)
#define NSTAGE 3
#define TC_SMEM (NSTAGE*(2*A_ELEMS + 2*B_ELEMS)*2)

__device__ __forceinline__ void mma16816(float* c, const uint32_t* a, const uint32_t* b){
    asm volatile(
      "mma.sync.aligned.m16n8k16.row.col.f32.f16.f16.f32 "
      "{%0,%1,%2,%3}, {%4,%5,%6,%7}, {%8,%9}, {%0,%1,%2,%3};"
      : "+f"(c[0]),"+f"(c[1]),"+f"(c[2]),"+f"(c[3])
      : "r"(a[0]),"r"(a[1]),"r"(a[2]),"r"(a[3]), "r"(b[0]),"r"(b[1]));
}
__device__ __forceinline__ void ldmx4(uint32_t* r, uint32_t addr){
    asm volatile("ldmatrix.sync.aligned.m8n8.x4.shared.b16 {%0,%1,%2,%3}, [%4];"
        : "=r"(r[0]),"=r"(r[1]),"=r"(r[2]),"=r"(r[3]) : "r"(addr));
}
__device__ __forceinline__ uint32_t smem_u32(const void* p){
    uint32_t a;
    asm("{ .reg .u64 t; cvta.to.shared.u64 t, %1; cvt.u32.u64 %0, t; }" : "=r"(a) : "l"(p));
    return a;
}
__device__ __forceinline__ void cpa16(uint32_t dst, const void* src, int sz){
    asm volatile("cp.async.cg.shared.global [%0], [%1], 16, %2;"
        :: "r"(dst), "l"(src), "r"(sz) : "memory");
}

// EPI: 0 = f32 out; 1 = gelu -> split; 2 = plain -> split; 3 = +bias,gelu -> f32
template<int EPI>
__device__ void mma_tile(const __half* Ah, const __half* Al,
                         const __half* Bh, const __half* Bl,
                         float* Cf, __half* Coh, __half* Col,
                         const float* bias, int M, int K, int mbase, int nbase)
{
    extern __shared__ __align__(16) char dsm[];
    __half* sA = (__half*)dsm;                  // [3 buf][2 split][64][40]
    __half* sB = sA + 2*NSTAGE*A_ELEMS;         // [3 buf][2 split][128][40]
    const int t = threadIdx.x;
    const int lane = t & 31, wid = t >> 5;
    const int wm = (wid >> 2) * 32, wn = (wid & 3) * 32;
    const int lr = lane >> 2, lc = (lane & 3) * 2;
    const int l7 = lane & 7, l8 = (lane >> 3) & 1, l16 = lane >> 4;

    const uint32_t sAu = smem_u32(sA);
    const uint32_t sBu = smem_u32(sB);

    float acc[2][4][4];
#pragma unroll
    for (int i=0;i<2;i++)
#pragma unroll
        for (int j=0;j<4;j++)
#pragma unroll
            for (int q=0;q<4;q++) acc[i][j][q] = 0.f;

    const int KT = K >> 5;

    auto prefetch = [&](int buf, int k0){
#pragma unroll
        for (int i=0;i<6;i++){
            int u = i*256 + t;
            if (u < 512){
                int sp = u >> 8, rem = u & 255;
                int r = rem >> 2, q = (rem & 3) * 8;
                int gm = mbase + r;
                int ok = (gm < M);
                const __half* src = (sp==0 ? Ah : Al) + (size_t)(ok ? gm : 0)*K + k0 + q;
                uint32_t doff = (uint32_t)(((buf*2 + sp)*64 + r)*STRD + q)*2;
                cpa16(sAu + doff, src, ok ? 16 : 0);
            } else {
                int v = u - 512;
                int sp = v >> 9, rem = v & 511;
                int r = rem >> 2, q = (rem & 3) * 8;
                const __half* src = (sp==0 ? Bh : Bl) + (size_t)(nbase + r)*K + k0 + q;
                uint32_t doff = (uint32_t)(((buf*2 + sp)*128 + r)*STRD + q)*2;
                cpa16(sBu + doff, src, 16);
            }
        }
        asm volatile("cp.async.commit_group;" ::: "memory");
    };

    prefetch(0, 0);
    prefetch(1, 32);

    for (int ch = 0; ch < KT; ch++){
        if (ch + 2 < KT){
            prefetch((ch+2)%NSTAGE, (ch+2)<<5);
            asm volatile("cp.async.wait_group 2;" ::: "memory");
        } else if (ch + 1 < KT){
            asm volatile("cp.async.wait_group 1;" ::: "memory");
        } else {
            asm volatile("cp.async.wait_group 0;" ::: "memory");
        }
        __syncthreads();
        const int buf = ch % NSTAGE;
        const uint32_t aHb = sAu + (uint32_t)((buf*2+0)*A_ELEMS)*2;
        const uint32_t aLb = sAu + (uint32_t)((buf*2+1)*A_ELEMS)*2;
        const uint32_t bHb = sBu + (uint32_t)((buf*2+0)*B_ELEMS)*2;
        const uint32_t bLb = sBu + (uint32_t)((buf*2+1)*B_ELEMS)*2;
#pragma unroll
        for (int s=0; s<32; s+=16){
            const uint32_t aoff = (uint32_t)((wm + l7 + l8*8)*STRD + s + l16*8)*2;
            const uint32_t boff = (uint32_t)((wn + l7 + l16*8)*STRD + s + l8*8)*2;
            // pass 0: aH x bH
            uint32_t aH[2][4], bH[4][2];
#pragma unroll
            for (int mt=0;mt<2;mt++)
                ldmx4(aH[mt], aHb + aoff + (uint32_t)(mt*16*STRD)*2);
#pragma unroll
            for (int np=0;np<2;np++){
                uint32_t rh[4];
                ldmx4(rh, bHb + boff + (uint32_t)(np*16*STRD)*2);
                bH[np*2][0]=rh[0]; bH[np*2][1]=rh[1]; bH[np*2+1][0]=rh[2]; bH[np*2+1][1]=rh[3];
            }
#pragma unroll
            for (int mt=0;mt<2;mt++)
#pragma unroll
                for (int nt=0;nt<4;nt++)
                    mma16816(acc[mt][nt], aH[mt], bH[nt]);
            // pass 1: aH x bL
            {
                uint32_t bL[4][2];
#pragma unroll
                for (int np=0;np<2;np++){
                    uint32_t rl[4];
                    ldmx4(rl, bLb + boff + (uint32_t)(np*16*STRD)*2);
                    bL[np*2][0]=rl[0]; bL[np*2][1]=rl[1]; bL[np*2+1][0]=rl[2]; bL[np*2+1][1]=rl[3];
                }
#pragma unroll
                for (int mt=0;mt<2;mt++)
#pragma unroll
                    for (int nt=0;nt<4;nt++)
                        mma16816(acc[mt][nt], aH[mt], bL[nt]);
            }
            // pass 2: aL x bH
            {
                uint32_t aL[2][4];
#pragma unroll
                for (int mt=0;mt<2;mt++)
                    ldmx4(aL[mt], aLb + aoff + (uint32_t)(mt*16*STRD)*2);
#pragma unroll
                for (int mt=0;mt<2;mt++)
#pragma unroll
                    for (int nt=0;nt<4;nt++)
                        mma16816(acc[mt][nt], aL[mt], bH[nt]);
            }
        }
        __syncthreads();
    }

#pragma unroll
    for (int mt=0;mt<2;mt++){
#pragma unroll
        for (int half=0; half<2; half++){
            int gm = mbase + wm + mt*16 + lr + half*8;
            if (gm >= M) continue;
#pragma unroll
            for (int nt=0;nt<4;nt++){
                int gc = nbase + wn + nt*8 + lc;
                float v0 = acc[mt][nt][half*2 + 0];
                float v1 = acc[mt][nt][half*2 + 1];
                if (EPI == 3){
                    v0 += bias[(gm/50)*CDIM + gc];
                    v1 += bias[(gm/50)*CDIM + gc + 1];
                    v0 = gelu_f(v0); v1 = gelu_f(v1);
                }
                if (EPI == 1){ v0 = gelu_f(v0); v1 = gelu_f(v1); }
                if (EPI == 0 || EPI == 3){
                    float2 pv; pv.x = v0; pv.y = v1;
                    *(float2*)(Cf + (size_t)gm*CDIM + gc) = pv;
                } else {
                    __half h0,l0,h1,l1;
                    split2(v0, h0, l0); split2(v1, h1, l1);
                    uint32_t ph = ((uint32_t)__half_as_ushort(h1) << 16) | __half_as_ushort(h0);
                    uint32_t pl = ((uint32_t)__half_as_ushort(l1) << 16) | __half_as_ushort(l0);
                    *(uint32_t*)(Coh + (size_t)gm*CDIM + gc) = ph;
                    *(uint32_t*)(Col + (size_t)gm*CDIM + gc) = pl;
                }
            }
        }
    }
}

__global__ __launch_bounds__(256) void k_g1(){
    mma_tile<1>(g_a0h, g_a0l, g_wh+W_IN, g_wl+W_IN, nullptr, g_h0h, g_h0l,
                nullptr, ROWS, DIM, blockIdx.y*64, blockIdx.x*128);
}
__global__ __launch_bounds__(256) void k_qkv(){
    int s = blockIdx.x >> 1;
    float* C = (s==0) ? g_q : (s==1) ? g_k : g_v;
    mma_tile<0>(g_h0h, g_h0l, g_wh+W_Q+s*65536, g_wl+W_Q+s*65536, C, nullptr, nullptr,
                nullptr, ROWS, CDIM, blockIdx.y*64, (blockIdx.x & 1)*128);
}
__global__ __launch_bounds__(256) void k_wo(){
    mma_tile<2>(g_aoh, g_aol, g_wh+W_O, g_wl+W_O, nullptr, g_h1h, g_h1l,
                nullptr, ROWS, CDIM, blockIdx.y*64, blockIdx.x*128);
}
__global__ __launch_bounds__(256) void k_gb(){
    mma_tile<0>(g_gmh, g_gml, g_wh+W_1B, g_wl+W_1B, g_gb, nullptr, nullptr,
                nullptr, BF, CDIM, blockIdx.y*64, blockIdx.x*128);
}
__global__ __launch_bounds__(256) void k_g2(){
    mma_tile<3>(g_h1h, g_h1l, g_wh+W_1A, g_wl+W_1A, g_h2, nullptr, nullptr,
                g_gb, ROWS, CDIM, blockIdx.y*64, blockIdx.x*128);
}

// ===================== attention ============================================
__global__ __launch_bounds__(256)
void attn_k(const float* __restrict__ q, const float* __restrict__ kk_,
            const float* __restrict__ v)
{
    __shared__ float Qs[64][65];
    __shared__ float Ks[64][65];
    __shared__ float S [64][51];
    const int bh = blockIdx.x;
    const int b = bh >> 1, h = bh & 1;
    const int base = b*NTOK*CDIM + h*128;
    const int tid = threadIdx.x;
    const int tx = tid & 15, ty = tid >> 4;
    float acc[4][4];
#pragma unroll
    for (int i=0;i<4;i++)
#pragma unroll
        for (int j=0;j<4;j++) acc[i][j]=0.f;
    for (int half=0; half<2; half++){
        for (int e=tid; e<4096; e+=256){
            int n = e >> 6, d = e & 63;
            float qv = 0.f, kv = 0.f;
            if (n < NTOK){
                qv = q  [base + n*CDIM + half*64 + d];
                kv = kk_[base + n*CDIM + half*64 + d];
            }
            Qs[n][d] = qv; Ks[n][d] = kv;
        }
        __syncthreads();
#pragma unroll 8
        for (int d=0; d<64; d++){
            float qf[4], kf[4];
#pragma unroll
            for (int i=0;i<4;i++) qf[i]=Qs[ty*4+i][d];
#pragma unroll
            for (int j=0;j<4;j++) kf[j]=Ks[tx*4+j][d];
#pragma unroll
            for (int i=0;i<4;i++)
#pragma unroll
                for (int j=0;j<4;j++) acc[i][j] += qf[i]*kf[j];
        }
        __syncthreads();
    }
    const float scale = 0.08838834764831845f;
#pragma unroll
    for (int i=0;i<4;i++)
#pragma unroll
        for (int j=0;j<4;j++){
            int qi = ty*4+i, ki = tx*4+j;
            if (ki < NTOK) S[qi][ki] = acc[i][j]*scale;
        }
    __syncthreads();
    {
        int warp = tid >> 5, lane = tid & 31;
        for (int r = warp; r < NTOK; r += 8){
            float v0 = S[r][lane];
            float v1 = (lane < 18) ? S[r][lane+32] : -3.4e38f;
            float m = fmaxf(v0, v1);
#pragma unroll
            for (int off=16; off; off>>=1) m = fmaxf(m, __shfl_xor_sync(FULLMASK, m, off));
            float e0 = expf(v0 - m);
            float e1 = (lane < 18) ? expf(v1 - m) : 0.f;
            float s = e0 + e1;
#pragma unroll
            for (int off=16; off; off>>=1) s += __shfl_xor_sync(FULLMASK, s, off);
            float inv = 1.f/s;
            S[r][lane] = e0*inv;
            if (lane < 18) S[r][lane+32] = e1*inv;
        }
    }
    __syncthreads();
    for (int half=0; half<2; half++){
        for (int e=tid; e<3200; e+=256){
            int n = e >> 6, d = e & 63;
            Qs[n][d] = v[base + n*CDIM + half*64 + d];
        }
        __syncthreads();
        float o[4][4];
#pragma unroll
        for (int i=0;i<4;i++)
#pragma unroll
            for (int j=0;j<4;j++) o[i][j]=0.f;
        for (int kv2=0; kv2<NTOK; kv2++){
            float af[4], vf[4];
#pragma unroll
            for (int i=0;i<4;i++) af[i] = S[ty*4+i][kv2];
#pragma unroll
            for (int j=0;j<4;j++) vf[j] = Qs[kv2][tx*4+j];
#pragma unroll
            for (int i=0;i<4;i++)
#pragma unroll
                for (int j=0;j<4;j++) o[i][j] += af[i]*vf[j];
        }
#pragma unroll
        for (int i=0;i<4;i++){
            int qi = ty*4+i;
            if (qi < NTOK){
#pragma unroll
                for (int j=0;j<4;j++){
                    int a = base + qi*CDIM + half*64 + tx*4+j;
                    __half hh, ll; split2(o[i][j], hh, ll);
                    g_aoh[a] = hh; g_aol[a] = ll;
                }
            }
        }
        __syncthreads();
    }
}

__global__ __launch_bounds__(256) void mean_kernel(){
    int b = blockIdx.x, c = threadIdx.x;
    float s = 0.f;
    for (int n=0;n<NTOK;n++){
        size_t a = (size_t)(b*NTOK+n)*CDIM + c;
        s += __half2float(g_h1h[a]) + __half2float(g_h1l[a]);
    }
    s *= (1.0f/50.0f);
    __half h, l; split2(s, h, l);
    g_gmh[b*CDIM + c] = h; g_gml[b*CDIM + c] = l;
}

__global__ __launch_bounds__(256) void pred_kernel(const float* __restrict__ w2){
    int gw = (blockIdx.x*256 + threadIdx.x) >> 5;
    if (gw >= ROWS) return;
    int lane = threadIdx.x & 31;
    const float* hr = g_h2 + (size_t)gw*CDIM;
    float s = 0.f;
#pragma unroll
    for (int i=0;i<8;i++) s += hr[lane + i*32] * w2[lane + i*32];
#pragma unroll
    for (int off=16; off; off>>=1) s += __shfl_xor_sync(FULLMASK, s, off);
    if (lane == 0) g_pred[gw] = tanhf(s);
}

__global__ __launch_bounds__(256) void zero_ind(){
    int i = blockIdx.x*256 + threadIdx.x;
    if (i < BF*KSEL*NSPA) g_ind[i] = 0.f;
}

__device__ __forceinline__ unsigned f2key(float f){
    unsigned b = __float_as_uint(f);
    return b ^ (unsigned)(((int)b >> 31) | 0x80000000);
}

__global__ __launch_bounds__(256) void topk_kernel(){
    int gw = (blockIdx.x*256 + threadIdx.x) >> 5;
    if (gw >= BF*NSAMP) return;
    int lane = threadIdx.x & 31;
    int b = gw / NSAMP;
    const float* sc = g_pred + b*NTOK + 2;
    const float* nz = g_noise + (size_t)gw*NSPA;
    float c0 = __fadd_rn(sc[lane], __fmul_rn(nz[lane], 0.05f));
    unsigned k0 = f2key(c0);
    unsigned k1 = 0u;
    if (lane < 16){
        float c1 = __fadd_rn(sc[lane+32], __fmul_rn(nz[lane+32], 0.05f));
        k1 = f2key(c1);
    }
    bool ch0 = false, ch1 = false;
#pragma unroll
    for (int it=0; it<KSEL; it++){
        unsigned m = (k0 > k1) ? k0 : k1;
        unsigned r = __reduce_max_sync(FULLMASK, m);
        unsigned b0 = __ballot_sync(FULLMASK, k0 == r);
        unsigned b1 = __ballot_sync(FULLMASK, k1 == r);
        if (b0){
            if (lane == __ffs(b0) - 1){ ch0 = true; k0 = 0u; }
        } else {
            if (lane == __ffs(b1) - 1){ ch1 = true; k1 = 0u; }
        }
    }
    unsigned m0 = __ballot_sync(FULLMASK, ch0);
    unsigned m1 = __ballot_sync(FULLMASK, ch1);
    unsigned below = (1u << lane) - 1u;
    if (ch0){
        int rank = __popc(m0 & below);
        atomicAdd(&g_ind[(b*KSEL + rank)*NSPA + lane], 1.0f);
    }
    if (ch1){
        int rank = __popc(m0) + __popc(m1 & below);
        atomicAdd(&g_ind[(b*KSEL + rank)*NSPA + lane + 32], 1.0f);
    }
}

__global__ __launch_bounds__(512) void sel_kernel(const float* __restrict__ x,
                                                  float* __restrict__ out){
    __shared__ float sind[KSEL*NSPA];
    int b = blockIdx.x, tid = threadIdx.x;
    for (int e = tid; e < KSEL*NSPA; e += 512)
        sind[e] = g_ind[b*KSEL*NSPA + e] * (1.0f/500.0f);
    __syncthreads();
    int d = tid;
    float a[KSEL];
#pragma unroll
    for (int k2=0;k2<KSEL;k2++) a[k2]=0.f;
    for (int l=0;l<NSPA;l++){
        float f = x[(size_t)(b*NTOK + 2 + l)*DIM + d];
#pragma unroll
        for (int k2=0;k2<KSEL;k2++) a[k2] += sind[k2*NSPA + l] * f;
    }
    out[(size_t)(b*14 + 0)*DIM + d] = x[(size_t)(b*NTOK + 0)*DIM + d];
    out[(size_t)(b*14 + 1)*DIM + d] = x[(size_t)(b*NTOK + 1)*DIM + d];
#pragma unroll
    for (int k2=0;k2<KSEL;k2++)
        out[(size_t)(b*14 + 2 + k2)*DIM + d] = a[k2];
}

extern "C" void kernel_launch(void* const* d_in, const int* in_sizes, int n_in,
                              void* d_out, int out_size) {
    const float* x    = (const float*)d_in[0];
    const float* ln_g = (const float*)d_in[1];
    const float* ln_b = (const float*)d_in[2];
    const float* w_in = (const float*)d_in[3];
    const float* wq   = (const float*)d_in[4];
    const float* wk   = (const float*)d_in[5];
    const float* wv   = (const float*)d_in[6];
    const float* wo   = (const float*)d_in[7];
    const float* w1   = (const float*)d_in[8];
    const float* w2   = (const float*)d_in[9];
    float* out = (float*)d_out;

    float *p_q, *p_k, *p_v;
    cudaGetSymbolAddress((void**)&p_q, g_q);
    cudaGetSymbolAddress((void**)&p_k, g_k);
    cudaGetSymbolAddress((void**)&p_v, g_v);

    static cudaStream_t s2 = nullptr;
    static cudaEvent_t ev_fork = nullptr, ev_noise = nullptr;
    if (!s2){
        cudaStreamCreateWithFlags(&s2, cudaStreamNonBlocking);
        cudaEventCreateWithFlags(&ev_fork,  cudaEventDisableTiming);
        cudaEventCreateWithFlags(&ev_noise, cudaEventDisableTiming);
        cudaFuncSetAttribute(k_g1,  cudaFuncAttributeMaxDynamicSharedMemorySize, TC_SMEM);
        cudaFuncSetAttribute(k_qkv, cudaFuncAttributeMaxDynamicSharedMemorySize, TC_SMEM);
        cudaFuncSetAttribute(k_wo,  cudaFuncAttributeMaxDynamicSharedMemorySize, TC_SMEM);
        cudaFuncSetAttribute(k_gb,  cudaFuncAttributeMaxDynamicSharedMemorySize, TC_SMEM);
        cudaFuncSetAttribute(k_g2,  cudaFuncAttributeMaxDynamicSharedMemorySize, TC_SMEM);
    }

    cudaEventRecord(ev_fork, 0);
    cudaStreamWaitEvent(s2, ev_fork, 0);
    noise_kernel<<<NOISE_N/1024, 256, 0, s2>>>();
    cudaEventRecord(ev_noise, s2);

    wcvt<<<W_TOT/256, 256>>>(w_in, wq, wk, wv, wo, w1);
    ln_cvt<<<1200, 256>>>(x, ln_g, ln_b);
    k_g1 <<<dim3(2,150), 256, TC_SMEM>>>();
    k_qkv<<<dim3(6,150), 256, TC_SMEM>>>();
    attn_k<<<BF*2, 256>>>(p_q, p_k, p_v);
    k_wo <<<dim3(2,150), 256, TC_SMEM>>>();
    mean_kernel<<<BF, 256>>>();
    k_gb <<<dim3(2,3), 256, TC_SMEM>>>();
    k_g2 <<<dim3(2,150), 256, TC_SMEM>>>();
    pred_kernel<<<1200, 256>>>(w2);
    zero_ind<<<(BF*KSEL*NSPA + 255)/256, 256>>>();

    cudaStreamWaitEvent(0, ev_noise, 0);
    topk_kernel<<<BF*NSAMP/8, 256>>>();
    sel_kernel<<<BF, 512>>>(x, out);
}

// round 13
// speedup vs baseline: 1.0462x; 1.0462x over previous
#include <cuda_runtime.h>
#include <cuda_fp16.h>
#include <cstdint>
#include <math.h>

#define FULLMASK 0xFFFFFFFFu
#define BF    192
#define NTOK  50
#define DIM   512
#define CDIM  256
#define ROWS  (BF*NTOK)
#define NSAMP 500
#define NSPA  48
#define KSEL  12
#define NOISE_N (192u*500u*48u)

#define W_IN  0
#define W_Q   131072
#define W_K   196608
#define W_V   262144
#define W_O   327680
#define W_1A  393216
#define W_1B  458752
#define W_TOT 524288

__device__ __align__(16) __half g_a0h[ROWS*DIM];
__device__ __align__(16) __half g_a0l[ROWS*DIM];
__device__ __align__(16) __half g_wh[W_TOT];
__device__ __align__(16) __half g_wl[W_TOT];
__device__ __align__(16) __half g_h0h[ROWS*CDIM];
__device__ __align__(16) __half g_h0l[ROWS*CDIM];
__device__ __align__(16) float g_q [ROWS*CDIM];
__device__ __align__(16) float g_k [ROWS*CDIM];
__device__ __align__(16) float g_v [ROWS*CDIM];
__device__ __align__(16) __half g_aoh[ROWS*CDIM];
__device__ __align__(16) __half g_aol[ROWS*CDIM];
__device__ __align__(16) __half g_h1h[ROWS*CDIM];
__device__ __align__(16) __half g_h1l[ROWS*CDIM];
__device__ __align__(16) __half g_gmh[BF*CDIM];
__device__ __align__(16) __half g_gml[BF*CDIM];
__device__ __align__(16) float g_gb[BF*CDIM];
__device__ __align__(16) float g_h2[ROWS*CDIM];
__device__ float g_pred[ROWS];
__device__ float g_noise[NOISE_N];
__device__ float g_ind[BF*KSEL*NSPA];

__device__ __forceinline__ float gelu_f(float x){
    return 0.5f * x * (1.0f + erff(x * 0.7071067811865475f));
}
__device__ __forceinline__ void split2(float v, __half& h, __half& l){
    h = __float2half_rn(v);
    l = __float2half_rn(v - __half2float(h));
}
__device__ __forceinline__ unsigned rotl32(unsigned x, int r){
    return __funnelshift_l(x, x, r);
}
__device__ __forceinline__ void threefry(unsigned& x0, unsigned& x1){
    const unsigned ks1 = 1u, ks2 = 0x1BD11BDBu;
    x1 += ks1;
#define RND(r) { x0 += x1; x1 = rotl32(x1,(r)); x1 ^= x0; }
    RND(13) RND(15) RND(26) RND(6)
    x0 += ks1; x1 += ks2 + 1u;
    RND(17) RND(29) RND(16) RND(24)
    x0 += ks2; x1 += 2u;
    RND(13) RND(15) RND(26) RND(6)
    x1 += ks1 + 3u;
    RND(17) RND(29) RND(16) RND(24)
    x0 += ks1; x1 += ks2 + 4u;
    RND(13) RND(15) RND(26) RND(6)
    x0 += ks2; x1 += 5u;
#undef RND
}
__device__ __forceinline__ float bits_to_normal(unsigned bits){
    float f = __uint_as_float((bits >> 9) | 0x3f800000u) - 1.0f;
    const float lo = -0.99999994f;
    float u = fmaxf(lo, __fadd_rn(__fmul_rn(f, 2.0f), lo));
    return 1.4142135623730951f * erfinvf(u);
}

__global__ __launch_bounds__(256) void noise_kernel(){
    unsigned i = (blockIdx.x*256u + threadIdx.x)*4u;
    float o[4];
#pragma unroll
    for (int j=0;j<4;j++){
        unsigned x0 = 0u, x1 = i + j;
        threefry(x0, x1);
        o[j] = bits_to_normal(x0 ^ x1);
    }
    float4 v; v.x=o[0]; v.y=o[1]; v.z=o[2]; v.w=o[3];
    *(float4*)(g_noise + i) = v;
}

// fused: blocks [0,1200) layernorm+split; blocks [1200, 1200+2048) weight cvt
__global__ __launch_bounds__(256) void prep_kernel(const float* __restrict__ x,
                                                   const float* __restrict__ g,
                                                   const float* __restrict__ b,
                                                   const float* __restrict__ w_in,
                                                   const float* __restrict__ wq,
                                                   const float* __restrict__ wk,
                                                   const float* __restrict__ wv,
                                                   const float* __restrict__ wo,
                                                   const float* __restrict__ w1){
    if (blockIdx.x < 1200){
        int row = (blockIdx.x*256 + threadIdx.x) >> 5;
        if (row >= ROWS) return;
        int lane = threadIdx.x & 31;
        const float* xr = x + (size_t)row*DIM;
        float vals[16], s = 0.f, s2 = 0.f;
#pragma unroll
        for (int i=0;i<16;i++){ float v = xr[lane + i*32]; vals[i]=v; s += v; s2 += v*v; }
#pragma unroll
        for (int off=16; off; off>>=1){
            s  += __shfl_xor_sync(FULLMASK, s,  off);
            s2 += __shfl_xor_sync(FULLMASK, s2, off);
        }
        float mu  = s * (1.0f/512.0f);
        float var = s2 * (1.0f/512.0f) - mu*mu;
        float rs  = rsqrtf(var + 1e-5f);
#pragma unroll
        for (int i=0;i<16;i++){
            int c = lane + i*32;
            float v = (vals[i]-mu)*rs * g[c] + b[c];
            __half h, l; split2(v, h, l);
            g_a0h[(size_t)row*DIM + c] = h;
            g_a0l[(size_t)row*DIM + c] = l;
        }
    } else {
        int idx = (blockIdx.x - 1200)*256 + threadIdx.x;
        if (idx >= W_TOT) return;
        float v;
        if (idx < W_Q){       int li=idx;       int n=li>>9, k=li&511; v = w_in[k*256+n]; }
        else if (idx < W_K){  int li=idx-W_Q;   int n=li>>8, k=li&255; v = wq[k*256+n]; }
        else if (idx < W_V){  int li=idx-W_K;   int n=li>>8, k=li&255; v = wk[k*256+n]; }
        else if (idx < W_O){  int li=idx-W_V;   int n=li>>8, k=li&255; v = wv[k*256+n]; }
        else if (idx < W_1A){ int li=idx-W_O;   int n=li>>8, k=li&255; v = wo[k*256+n]; }
        else if (idx < W_1B){ int li=idx-W_1A;  int n=li>>8, k=li&255; v = w1[k*256+n]; }
        else {                int li=idx-W_1B;  int n=li>>8, k=li&255; v = w1[(k+256)*256+n]; }
        __half h, l; split2(v, h, l);
        g_wh[idx] = h; g_wl[idx] = l;
    }
}

// ===================== mma.sync fp16-split GEMM: 64x128 tile, 2-stage =======
#define STRD 40
#define A_ELEMS (64*STRD)
#define B_ELEMS (128*STRD)
#define TC_SMEM ((4*A_ELEMS + 4*B_ELEMS)*2)

__device__ __forceinline__ void mma16816(float* c, const uint32_t* a, const uint32_t* b){
    asm volatile(
      "mma.sync.aligned.m16n8k16.row.col.f32.f16.f16.f32 "
      "{%0,%1,%2,%3}, {%4,%5,%6,%7}, {%8,%9}, {%0,%1,%2,%3};"
      : "+f"(c[0]),"+f"(c[1]),"+f"(c[2]),"+f"(c[3])
      : "r"(a[0]),"r"(a[1]),"r"(a[2]),"r"(a[3]), "r"(b[0]),"r"(b[1]));
}
__device__ __forceinline__ void ldmx4(uint32_t* r, uint32_t addr){
    asm volatile("ldmatrix.sync.aligned.m8n8.x4.shared.b16 {%0,%1,%2,%3}, [%4];"
        : "=r"(r[0]),"=r"(r[1]),"=r"(r[2]),"=r"(r[3]) : "r"(addr));
}
__device__ __forceinline__ uint32_t smem_u32(const void* p){
    uint32_t a;
    asm("{ .reg .u64 t; cvta.to.shared.u64 t, %1; cvt.u32.u64 %0, t; }" : "=r"(a) : "l"(p));
    return a;
}
__device__ __forceinline__ void cpa16(uint32_t dst, const void* src, int sz){
    asm volatile("cp.async.cg.shared.global [%0], [%1], 16, %2;"
        :: "r"(dst), "l"(src), "r"(sz) : "memory");
}

// EPI: 0 = f32 out; 1 = gelu -> split; 2 = plain -> split; 3 = +bias,gelu -> f32
template<int EPI>
__device__ void mma_tile(const __half* Ah, const __half* Al,
                         const __half* Bh, const __half* Bl,
                         float* Cf, __half* Coh, __half* Col,
                         const float* bias, int M, int K, int mbase, int nbase)
{
    extern __shared__ __align__(16) char dsm[];
    __half* sA = (__half*)dsm;                 // [2 buf][2 split][64][40]
    __half* sB = sA + 4*A_ELEMS;               // [2 buf][2 split][128][40]
    const int t = threadIdx.x;
    const int lane = t & 31, wid = t >> 5;
    const int wm = (wid >> 2) * 32, wn = (wid & 3) * 32;
    const int lr = lane >> 2, lc = (lane & 3) * 2;
    const int l7 = lane & 7, l8 = (lane >> 3) & 1, l16 = lane >> 4;

    const uint32_t sAu = smem_u32(sA);
    const uint32_t sBu = smem_u32(sB);

    float acc[2][4][4];
#pragma unroll
    for (int i=0;i<2;i++)
#pragma unroll
        for (int j=0;j<4;j++)
#pragma unroll
            for (int q=0;q<4;q++) acc[i][j][q] = 0.f;

    const int KT = K >> 5;

    auto prefetch = [&](int buf, int k0){
#pragma unroll
        for (int i=0;i<6;i++){
            int u = i*256 + t;
            if (u < 512){
                int sp = u >> 8, rem = u & 255;
                int r = rem >> 2, q = (rem & 3) * 8;
                int gm = mbase + r;
                int ok = (gm < M);
                const __half* src = (sp==0 ? Ah : Al) + (size_t)(ok ? gm : 0)*K + k0 + q;
                uint32_t doff = (uint32_t)(((buf*2 + sp)*64 + r)*STRD + q)*2;
                cpa16(sAu + doff, src, ok ? 16 : 0);
            } else {
                int v = u - 512;
                int sp = v >> 9, rem = v & 511;
                int r = rem >> 2, q = (rem & 3) * 8;
                const __half* src = (sp==0 ? Bh : Bl) + (size_t)(nbase + r)*K + k0 + q;
                uint32_t doff = (uint32_t)(((buf*2 + sp)*128 + r)*STRD + q)*2;
                cpa16(sBu + doff, src, 16);
            }
        }
        asm volatile("cp.async.commit_group;" ::: "memory");
    };

    prefetch(0, 0);

    for (int ch = 0; ch < KT; ch++){
        if (ch + 1 < KT){
            prefetch((ch+1)&1, (ch+1)<<5);
            asm volatile("cp.async.wait_group 1;" ::: "memory");
        } else {
            asm volatile("cp.async.wait_group 0;" ::: "memory");
        }
        __syncthreads();
        const int buf = ch & 1;
        const uint32_t aHb = sAu + (uint32_t)((buf*2+0)*A_ELEMS)*2;
        const uint32_t aLb = sAu + (uint32_t)((buf*2+1)*A_ELEMS)*2;
        const uint32_t bHb = sBu + (uint32_t)((buf*2+0)*B_ELEMS)*2;
        const uint32_t bLb = sBu + (uint32_t)((buf*2+1)*B_ELEMS)*2;
#pragma unroll
        for (int s=0; s<32; s+=16){
            const uint32_t aoff = (uint32_t)((wm + l7 + l8*8)*STRD + s + l16*8)*2;
            const uint32_t boff = (uint32_t)((wn + l7 + l16*8)*STRD + s + l8*8)*2;
            // pass 0: aH x bH
            uint32_t aH[2][4], bH[4][2];
#pragma unroll
            for (int mt=0;mt<2;mt++)
                ldmx4(aH[mt], aHb + aoff + (uint32_t)(mt*16*STRD)*2);
#pragma unroll
            for (int np=0;np<2;np++){
                uint32_t rh[4];
                ldmx4(rh, bHb + boff + (uint32_t)(np*16*STRD)*2);
                bH[np*2][0]=rh[0]; bH[np*2][1]=rh[1]; bH[np*2+1][0]=rh[2]; bH[np*2+1][1]=rh[3];
            }
#pragma unroll
            for (int mt=0;mt<2;mt++)
#pragma unroll
                for (int nt=0;nt<4;nt++)
                    mma16816(acc[mt][nt], aH[mt], bH[nt]);
            // pass 1: aH x bL
            {
                uint32_t bL[4][2];
#pragma unroll
                for (int np=0;np<2;np++){
                    uint32_t rl[4];
                    ldmx4(rl, bLb + boff + (uint32_t)(np*16*STRD)*2);
                    bL[np*2][0]=rl[0]; bL[np*2][1]=rl[1]; bL[np*2+1][0]=rl[2]; bL[np*2+1][1]=rl[3];
                }
#pragma unroll
                for (int mt=0;mt<2;mt++)
#pragma unroll
                    for (int nt=0;nt<4;nt++)
                        mma16816(acc[mt][nt], aH[mt], bL[nt]);
            }
            // pass 2: aL x bH
            {
                uint32_t aL[2][4];
#pragma unroll
                for (int mt=0;mt<2;mt++)
                    ldmx4(aL[mt], aLb + aoff + (uint32_t)(mt*16*STRD)*2);
#pragma unroll
                for (int mt=0;mt<2;mt++)
#pragma unroll
                    for (int nt=0;nt<4;nt++)
                        mma16816(acc[mt][nt], aL[mt], bH[nt]);
            }
        }
        __syncthreads();
    }

#pragma unroll
    for (int mt=0;mt<2;mt++){
#pragma unroll
        for (int half=0; half<2; half++){
            int gm = mbase + wm + mt*16 + lr + half*8;
            if (gm >= M) continue;
#pragma unroll
            for (int nt=0;nt<4;nt++){
                int gc = nbase + wn + nt*8 + lc;
                float v0 = acc[mt][nt][half*2 + 0];
                float v1 = acc[mt][nt][half*2 + 1];
                if (EPI == 3){
                    v0 += bias[(gm/50)*CDIM + gc];
                    v1 += bias[(gm/50)*CDIM + gc + 1];
                    v0 = gelu_f(v0); v1 = gelu_f(v1);
                }
                if (EPI == 1){ v0 = gelu_f(v0); v1 = gelu_f(v1); }
                if (EPI == 0 || EPI == 3){
                    float2 pv; pv.x = v0; pv.y = v1;
                    *(float2*)(Cf + (size_t)gm*CDIM + gc) = pv;
                } else {
                    __half h0,l0,h1,l1;
                    split2(v0, h0, l0); split2(v1, h1, l1);
                    uint32_t ph = ((uint32_t)__half_as_ushort(h1) << 16) | __half_as_ushort(h0);
                    uint32_t pl = ((uint32_t)__half_as_ushort(l1) << 16) | __half_as_ushort(l0);
                    *(uint32_t*)(Coh + (size_t)gm*CDIM + gc) = ph;
                    *(uint32_t*)(Col + (size_t)gm*CDIM + gc) = pl;
                }
            }
        }
    }
}

__global__ __launch_bounds__(256) void k_g1(){
    mma_tile<1>(g_a0h, g_a0l, g_wh+W_IN, g_wl+W_IN, nullptr, g_h0h, g_h0l,
                nullptr, ROWS, DIM, blockIdx.y*64, blockIdx.x*128);
}
__global__ __launch_bounds__(256) void k_qkv(){
    int s = blockIdx.x >> 1;
    float* C = (s==0) ? g_q : (s==1) ? g_k : g_v;
    mma_tile<0>(g_h0h, g_h0l, g_wh+W_Q+s*65536, g_wl+W_Q+s*65536, C, nullptr, nullptr,
                nullptr, ROWS, CDIM, blockIdx.y*64, (blockIdx.x & 1)*128);
}
__global__ __launch_bounds__(256) void k_wo(){
    mma_tile<2>(g_aoh, g_aol, g_wh+W_O, g_wl+W_O, nullptr, g_h1h, g_h1l,
                nullptr, ROWS, CDIM, blockIdx.y*64, blockIdx.x*128);
}
__global__ __launch_bounds__(256) void k_gb(){
    mma_tile<0>(g_gmh, g_gml, g_wh+W_1B, g_wl+W_1B, g_gb, nullptr, nullptr,
                nullptr, BF, CDIM, blockIdx.y*64, blockIdx.x*128);
}
__global__ __launch_bounds__(256) void k_g2(){
    mma_tile<3>(g_h1h, g_h1l, g_wh+W_1A, g_wl+W_1A, g_h2, nullptr, nullptr,
                g_gb, ROWS, CDIM, blockIdx.y*64, blockIdx.x*128);
}

// ===================== attention ============================================
__global__ __launch_bounds__(256)
void attn_k(const float* __restrict__ q, const float* __restrict__ kk_,
            const float* __restrict__ v)
{
    __shared__ float Qs[64][65];
    __shared__ float Ks[64][65];
    __shared__ float S [64][51];
    const int bh = blockIdx.x;
    const int b = bh >> 1, h = bh & 1;
    const int base = b*NTOK*CDIM + h*128;
    const int tid = threadIdx.x;
    const int tx = tid & 15, ty = tid >> 4;
    float acc[4][4];
#pragma unroll
    for (int i=0;i<4;i++)
#pragma unroll
        for (int j=0;j<4;j++) acc[i][j]=0.f;
    for (int half=0; half<2; half++){
        for (int e=tid; e<4096; e+=256){
            int n = e >> 6, d = e & 63;
            float qv = 0.f, kv = 0.f;
            if (n < NTOK){
                qv = q  [base + n*CDIM + half*64 + d];
                kv = kk_[base + n*CDIM + half*64 + d];
            }
            Qs[n][d] = qv; Ks[n][d] = kv;
        }
        __syncthreads();
#pragma unroll 8
        for (int d=0; d<64; d++){
            float qf[4], kf[4];
#pragma unroll
            for (int i=0;i<4;i++) qf[i]=Qs[ty*4+i][d];
#pragma unroll
            for (int j=0;j<4;j++) kf[j]=Ks[tx*4+j][d];
#pragma unroll
            for (int i=0;i<4;i++)
#pragma unroll
                for (int j=0;j<4;j++) acc[i][j] += qf[i]*kf[j];
        }
        __syncthreads();
    }
    const float scale = 0.08838834764831845f;
#pragma unroll
    for (int i=0;i<4;i++)
#pragma unroll
        for (int j=0;j<4;j++){
            int qi = ty*4+i, ki = tx*4+j;
            if (ki < NTOK) S[qi][ki] = acc[i][j]*scale;
        }
    __syncthreads();
    {
        int warp = tid >> 5, lane = tid & 31;
        for (int r = warp; r < NTOK; r += 8){
            float v0 = S[r][lane];
            float v1 = (lane < 18) ? S[r][lane+32] : -3.4e38f;
            float m = fmaxf(v0, v1);
#pragma unroll
            for (int off=16; off; off>>=1) m = fmaxf(m, __shfl_xor_sync(FULLMASK, m, off));
            float e0 = expf(v0 - m);
            float e1 = (lane < 18) ? expf(v1 - m) : 0.f;
            float s = e0 + e1;
#pragma unroll
            for (int off=16; off; off>>=1) s += __shfl_xor_sync(FULLMASK, s, off);
            float inv = 1.f/s;
            S[r][lane] = e0*inv;
            if (lane < 18) S[r][lane+32] = e1*inv;
        }
    }
    __syncthreads();
    for (int half=0; half<2; half++){
        for (int e=tid; e<3200; e+=256){
            int n = e >> 6, d = e & 63;
            Qs[n][d] = v[base + n*CDIM + half*64 + d];
        }
        __syncthreads();
        float o[4][4];
#pragma unroll
        for (int i=0;i<4;i++)
#pragma unroll
            for (int j=0;j<4;j++) o[i][j]=0.f;
        for (int kv2=0; kv2<NTOK; kv2++){
            float af[4], vf[4];
#pragma unroll
            for (int i=0;i<4;i++) af[i] = S[ty*4+i][kv2];
#pragma unroll
            for (int j=0;j<4;j++) vf[j] = Qs[kv2][tx*4+j];
#pragma unroll
            for (int i=0;i<4;i++)
#pragma unroll
                for (int j=0;j<4;j++) o[i][j] += af[i]*vf[j];
        }
#pragma unroll
        for (int i=0;i<4;i++){
            int qi = ty*4+i;
            if (qi < NTOK){
#pragma unroll
                for (int j=0;j<4;j++){
                    int a = base + qi*CDIM + half*64 + tx*4+j;
                    __half hh, ll; split2(o[i][j], hh, ll);
                    g_aoh[a] = hh; g_aol[a] = ll;
                }
            }
        }
        __syncthreads();
    }
}

__global__ __launch_bounds__(256) void mean_kernel(){
    int b = blockIdx.x, c = threadIdx.x;
    float s = 0.f;
    for (int n=0;n<NTOK;n++){
        size_t a = (size_t)(b*NTOK+n)*CDIM + c;
        s += __half2float(g_h1h[a]) + __half2float(g_h1l[a]);
    }
    s *= (1.0f/50.0f);
    __half h, l; split2(s, h, l);
    g_gmh[b*CDIM + c] = h; g_gml[b*CDIM + c] = l;
}

// fused: pred over ROWS warps + zero g_ind (blocks >= 1200)
__global__ __launch_bounds__(256) void pred_zero_kernel(const float* __restrict__ w2){
    if (blockIdx.x < 1200){
        int gw = (blockIdx.x*256 + threadIdx.x) >> 5;
        if (gw >= ROWS) return;
        int lane = threadIdx.x & 31;
        const float* hr = g_h2 + (size_t)gw*CDIM;
        float s = 0.f;
#pragma unroll
        for (int i=0;i<8;i++) s += hr[lane + i*32] * w2[lane + i*32];
#pragma unroll
        for (int off=16; off; off>>=1) s += __shfl_xor_sync(FULLMASK, s, off);
        if (lane == 0) g_pred[gw] = tanhf(s);
    } else {
        int i = (blockIdx.x - 1200)*256 + threadIdx.x;
        if (i < BF*KSEL*NSPA) g_ind[i] = 0.f;
    }
}

__device__ __forceinline__ unsigned f2key(float f){
    unsigned b = __float_as_uint(f);
    return b ^ (unsigned)(((int)b >> 31) | 0x80000000);
}

__global__ __launch_bounds__(256) void topk_kernel(){
    int gw = (blockIdx.x*256 + threadIdx.x) >> 5;
    if (gw >= BF*NSAMP) return;
    int lane = threadIdx.x & 31;
    int b = gw / NSAMP;
    const float* sc = g_pred + b*NTOK + 2;
    const float* nz = g_noise + (size_t)gw*NSPA;
    float c0 = __fadd_rn(sc[lane], __fmul_rn(nz[lane], 0.05f));
    unsigned k0 = f2key(c0);
    unsigned k1 = 0u;
    if (lane < 16){
        float c1 = __fadd_rn(sc[lane+32], __fmul_rn(nz[lane+32], 0.05f));
        k1 = f2key(c1);
    }
    bool ch0 = false, ch1 = false;
#pragma unroll
    for (int it=0; it<KSEL; it++){
        unsigned m = (k0 > k1) ? k0 : k1;
        unsigned r = __reduce_max_sync(FULLMASK, m);
        unsigned b0 = __ballot_sync(FULLMASK, k0 == r);
        unsigned b1 = __ballot_sync(FULLMASK, k1 == r);
        if (b0){
            if (lane == __ffs(b0) - 1){ ch0 = true; k0 = 0u; }
        } else {
            if (lane == __ffs(b1) - 1){ ch1 = true; k1 = 0u; }
        }
    }
    unsigned m0 = __ballot_sync(FULLMASK, ch0);
    unsigned m1 = __ballot_sync(FULLMASK, ch1);
    unsigned below = (1u << lane) - 1u;
    if (ch0){
        int rank = __popc(m0 & below);
        atomicAdd(&g_ind[(b*KSEL + rank)*NSPA + lane], 1.0f);
    }
    if (ch1){
        int rank = __popc(m0) + __popc(m1 & below);
        atomicAdd(&g_ind[(b*KSEL + rank)*NSPA + lane + 32], 1.0f);
    }
}

__global__ __launch_bounds__(512) void sel_kernel(const float* __restrict__ x,
                                                  float* __restrict__ out){
    __shared__ float sind[KSEL*NSPA];
    int b = blockIdx.x, tid = threadIdx.x;
    for (int e = tid; e < KSEL*NSPA; e += 512)
        sind[e] = g_ind[b*KSEL*NSPA + e] * (1.0f/500.0f);
    __syncthreads();
    int d = tid;
    float a[KSEL];
#pragma unroll
    for (int k2=0;k2<KSEL;k2++) a[k2]=0.f;
    for (int l=0;l<NSPA;l++){
        float f = x[(size_t)(b*NTOK + 2 + l)*DIM + d];
#pragma unroll
        for (int k2=0;k2<KSEL;k2++) a[k2] += sind[k2*NSPA + l] * f;
    }
    out[(size_t)(b*14 + 0)*DIM + d] = x[(size_t)(b*NTOK + 0)*DIM + d];
    out[(size_t)(b*14 + 1)*DIM + d] = x[(size_t)(b*NTOK + 1)*DIM + d];
#pragma unroll
    for (int k2=0;k2<KSEL;k2++)
        out[(size_t)(b*14 + 2 + k2)*DIM + d] = a[k2];
}

extern "C" void kernel_launch(void* const* d_in, const int* in_sizes, int n_in,
                              void* d_out, int out_size) {
    const float* x    = (const float*)d_in[0];
    const float* ln_g = (const float*)d_in[1];
    const float* ln_b = (const float*)d_in[2];
    const float* w_in = (const float*)d_in[3];
    const float* wq   = (const float*)d_in[4];
    const float* wk   = (const float*)d_in[5];
    const float* wv   = (const float*)d_in[6];
    const float* wo   = (const float*)d_in[7];
    const float* w1   = (const float*)d_in[8];
    const float* w2   = (const float*)d_in[9];
    float* out = (float*)d_out;

    float *p_q, *p_k, *p_v;
    cudaGetSymbolAddress((void**)&p_q, g_q);
    cudaGetSymbolAddress((void**)&p_k, g_k);
    cudaGetSymbolAddress((void**)&p_v, g_v);

    static cudaStream_t s2 = nullptr;
    static cudaEvent_t ev_fork = nullptr, ev_noise = nullptr;
    if (!s2){
        cudaStreamCreateWithFlags(&s2, cudaStreamNonBlocking);
        cudaEventCreateWithFlags(&ev_fork,  cudaEventDisableTiming);
        cudaEventCreateWithFlags(&ev_noise, cudaEventDisableTiming);
        cudaFuncSetAttribute(k_g1,  cudaFuncAttributeMaxDynamicSharedMemorySize, TC_SMEM);
        cudaFuncSetAttribute(k_qkv, cudaFuncAttributeMaxDynamicSharedMemorySize, TC_SMEM);
        cudaFuncSetAttribute(k_wo,  cudaFuncAttributeMaxDynamicSharedMemorySize, TC_SMEM);
        cudaFuncSetAttribute(k_gb,  cudaFuncAttributeMaxDynamicSharedMemorySize, TC_SMEM);
        cudaFuncSetAttribute(k_g2,  cudaFuncAttributeMaxDynamicSharedMemorySize, TC_SMEM);
    }

    cudaEventRecord(ev_fork, 0);
    cudaStreamWaitEvent(s2, ev_fork, 0);
    noise_kernel<<<NOISE_N/1024, 256, 0, s2>>>();
    cudaEventRecord(ev_noise, s2);

    prep_kernel<<<1200 + W_TOT/256, 256>>>(x, ln_g, ln_b, w_in, wq, wk, wv, wo, w1);
    k_g1 <<<dim3(2,150), 256, TC_SMEM>>>();
    k_qkv<<<dim3(6,150), 256, TC_SMEM>>>();
    attn_k<<<BF*2, 256>>>(p_q, p_k, p_v);
    k_wo <<<dim3(2,150), 256, TC_SMEM>>>();
    mean_kernel<<<BF, 256>>>();
    k_gb <<<dim3(2,3), 256, TC_SMEM>>>();
    k_g2 <<<dim3(2,150), 256, TC_SMEM>>>();
    pred_zero_kernel<<<1200 + (BF*KSEL*NSPA + 255)/256, 256>>>(w2);

    cudaStreamWaitEvent(0, ev_noise, 0);
    topk_kernel<<<BF*NSAMP/8, 256>>>();
    sel_kernel<<<BF, 512>>>(x, out);
}